// round 15
// baseline (speedup 1.0000x reference)
#include <cuda_runtime.h>
#include <cuda_bf16.h>

// Problem constants (fixed by setup_inputs):
// x_0  : [128, 64, 16] f32   (d_in[0])
// x_h  : [128, 64, 16] f32   (d_in[1], UNUSED — reference bug recomputes from x_0)
// Vm   : [64, 1, 64, 16] f32 (d_in[2])
// Vh   : [64, 1, 16, 64] f32 (d_in[3])
// out  : [128, 64, 16] f32
//
// out[b,k,d] = sum_v P[n,kv]*Q[n,kv], n = b*16+d, kv = k*16+v
//   P = Xa[2048x64] * Wm^T,  Q = Xb[2048x64] * Wh^T
// bf16 3-term split folded into K=192: A=[hi|lo|hi], B=[whi|whi|wlo].
//
// R15: GEMM CTA = 128n x 128kv, 8 warps (256 thr), warp tile 32n x 64kv.
// K-pipelined cp.async staging (2 commit groups), interleaved A/B mma loop,
// in-register dot epilogue.

#define CW 192           // composite K width (bf16)
#define NROWS 2048
#define KVROWS 1024
#define XROWB 400        // padded smem row stride in bytes

__device__ __nv_bfloat16 g_XaC[NROWS * CW];
__device__ __nv_bfloat16 g_XbC[NROWS * CW];
__device__ __nv_bfloat16 g_WmC[KVROWS * CW];
__device__ __nv_bfloat16 g_WhC[KVROWS * CW];

// ============================ prep kernel ============================
__global__ void __launch_bounds__(128)
prep_kernel(const float* __restrict__ x0,
            const float* __restrict__ Vm,
            const float* __restrict__ Vh)
{
    __shared__ float sp[64 * 17 + 17];
    const int tid = threadIdx.x;
    const int bid = blockIdx.x;

    const float* src;
    if (bid < 128)      src = x0 + bid * 1024;
    else if (bid < 192) src = Vm + (bid - 128) * 1024;
    else                src = Vh + (bid - 192) * 1024;

    const float4* s4 = reinterpret_cast<const float4*>(src);
    #pragma unroll
    for (int e = 0; e < 2; e++) {
        int f4 = tid + e * 128;
        float4 wv = s4[f4];
        int f = f4 * 4;
        float* dst = &sp[(f >> 4) * 17 + (f & 15)];
        dst[0] = wv.x; dst[1] = wv.y; dst[2] = wv.z; dst[3] = wv.w;
    }
    __syncthreads();

    const int r  = tid >> 3;          // d (X) or v (W), 0..15
    const int cb = (tid & 7) * 24;    // 24 consecutive c per thread

    if (bid < 128) {
        const int n = bid * 16 + r;
        unsigned ua[12], ub[12];
        #pragma unroll
        for (int p = 0; p < 12; p++) {
            unsigned short ha[2], hb[2];
            #pragma unroll
            for (int e = 0; e < 2; e++) {
                int c   = cb + p * 2 + e;
                int seg = c >> 6;             // 0: hi, 1: lo, 2: hi
                int idx = c & 63;
                float va = sp[idx * 17 + r];
                __nv_bfloat16 hia = __float2bfloat16(va);
                ha[e] = (seg == 1)
                    ? __bfloat16_as_ushort(__float2bfloat16(va - __bfloat162float(hia)))
                    : __bfloat16_as_ushort(hia);
                int f = r * 64 + idx;
                float vb = sp[(f >> 4) * 17 + (f & 15)];
                __nv_bfloat16 hib = __float2bfloat16(vb);
                hb[e] = (seg == 1)
                    ? __bfloat16_as_ushort(__float2bfloat16(vb - __bfloat162float(hib)))
                    : __bfloat16_as_ushort(hib);
            }
            ua[p] = (unsigned)ha[0] | ((unsigned)ha[1] << 16);
            ub[p] = (unsigned)hb[0] | ((unsigned)hb[1] << 16);
        }
        uint4* da = reinterpret_cast<uint4*>(g_XaC + n * CW + cb);
        da[0] = make_uint4(ua[0], ua[1], ua[2],  ua[3]);
        da[1] = make_uint4(ua[4], ua[5], ua[6],  ua[7]);
        da[2] = make_uint4(ua[8], ua[9], ua[10], ua[11]);
        uint4* db = reinterpret_cast<uint4*>(g_XbC + n * CW + cb);
        db[0] = make_uint4(ub[0], ub[1], ub[2],  ub[3]);
        db[1] = make_uint4(ub[4], ub[5], ub[6],  ub[7]);
        db[2] = make_uint4(ub[8], ub[9], ub[10], ub[11]);
    } else {
        const bool isWm = bid < 192;
        const int k  = isWm ? (bid - 128) : (bid - 192);
        const int kv = k * 16 + r;
        unsigned uw[12];
        #pragma unroll
        for (int p = 0; p < 12; p++) {
            unsigned short hw[2];
            #pragma unroll
            for (int e = 0; e < 2; e++) {
                int c   = cb + p * 2 + e;
                int seg = c >> 6;             // 0: hi, 1: hi, 2: lo
                int idx = c & 63;
                float val;
                if (isWm) val = sp[idx * 17 + r];
                else { int f = r * 64 + idx; val = sp[(f >> 4) * 17 + (f & 15)]; }
                __nv_bfloat16 hi = __float2bfloat16(val);
                hw[e] = (seg == 2)
                    ? __bfloat16_as_ushort(__float2bfloat16(val - __bfloat162float(hi)))
                    : __bfloat16_as_ushort(hi);
            }
            uw[p] = (unsigned)hw[0] | ((unsigned)hw[1] << 16);
        }
        __nv_bfloat16* base = isWm ? g_WmC : g_WhC;
        uint4* dw = reinterpret_cast<uint4*>(base + kv * CW + cb);
        dw[0] = make_uint4(uw[0], uw[1], uw[2],  uw[3]);
        dw[1] = make_uint4(uw[4], uw[5], uw[6],  uw[7]);
        dw[2] = make_uint4(uw[8], uw[9], uw[10], uw[11]);
    }
}

// ============================ GEMM kernel ============================
// CTA = 128 n-rows x 128 kv-cols. 8 warps (256 thr), warp tile 32n x 64kv.
// smem: Xa | Xb | Wm | Wh, each 128 rows x 400B = 51200 B. Total 204800 B.
#define SMEM_MAIN 204800
#define NTHR2 256
#define RSZ 51200u

__device__ __forceinline__ void ldsm_x4(unsigned& r0, unsigned& r1,
                                        unsigned& r2, unsigned& r3,
                                        unsigned addr) {
    asm volatile("ldmatrix.sync.aligned.m8n8.x4.shared.b16 {%0,%1,%2,%3}, [%4];"
        : "=r"(r0), "=r"(r1), "=r"(r2), "=r"(r3) : "r"(addr));
}
__device__ __forceinline__ void mma_bf16(float c[4],
        unsigned a0, unsigned a1, unsigned a2, unsigned a3,
        unsigned b0, unsigned b1) {
    asm volatile(
        "mma.sync.aligned.m16n8k16.row.col.f32.bf16.bf16.f32 "
        "{%0,%1,%2,%3},{%4,%5,%6,%7},{%8,%9},{%0,%1,%2,%3};"
        : "+f"(c[0]), "+f"(c[1]), "+f"(c[2]), "+f"(c[3])
        : "r"(a0), "r"(a1), "r"(a2), "r"(a3), "r"(b0), "r"(b1));
}
__device__ __forceinline__ void cp16(unsigned saddr, const void* gaddr) {
    asm volatile("cp.async.cg.shared.global [%0], [%1], 16;"
        :: "r"(saddr), "l"(gaddr));
}

__global__ void __launch_bounds__(NTHR2, 1)
cin_mma_kernel(float* __restrict__ out)
{
    extern __shared__ __align__(16) unsigned char smem[];
    const unsigned sXa = (unsigned)__cvta_generic_to_shared(smem);
    const unsigned sXb = sXa + RSZ;
    const unsigned sWm = sXa + 2u * RSZ;
    const unsigned sWh = sXa + 3u * RSZ;

    const int tid    = threadIdx.x;
    const int kvtile = blockIdx.x * 128;  // 8 kv-tiles (8 k each)
    const int ntile  = blockIdx.y * 128;  // 16 n-tiles
    const int k0     = blockIdx.x * 8;

    const uint4* gXa = reinterpret_cast<const uint4*>(g_XaC + ntile * CW);
    const uint4* gXb = reinterpret_cast<const uint4*>(g_XbC + ntile * CW);
    const uint4* gWm = reinterpret_cast<const uint4*>(g_WmC + kvtile * CW);
    const uint4* gWh = reinterpret_cast<const uint4*>(g_WhC + kvtile * CW);

    // ---- staging: two commit groups by K-halves (cols 0..95 | 96..191) ----
    // per group per region: 128 rows x 12 uint4 = 1536 elems / 256 thr = 6 each
    #pragma unroll
    for (int grp = 0; grp < 2; grp++) {
        #pragma unroll
        for (int e = 0; e < 6; e++) {
            int idx  = tid + e * NTHR2;       // 0..1535
            int row  = idx / 12;
            int c16  = idx - row * 12 + grp * 12;
            unsigned soff = (unsigned)(row * XROWB + c16 * 16);
            int gidx = row * 24 + c16;
            cp16(sXa + soff, gXa + gidx);
            cp16(sXb + soff, gXb + gidx);
            cp16(sWm + soff, gWm + gidx);
            cp16(sWh + soff, gWh + gidx);
        }
        asm volatile("cp.async.commit_group;");
    }

    // warp w: nw = w&3 (rows nw*32), kw = w>>2 (cols kw*64)
    const int w    = tid >> 5;
    const int lane = tid & 31;
    const int nw   = w & 3;
    const int kw   = w >> 2;
    const int g    = lane >> 2;
    const int q    = lane & 3;
    const int m    = lane >> 3;

    // A-frag lane addresses (m16k16 x4), two m-blocks per warp
    unsigned aA[2], aB[2];
    #pragma unroll
    for (int mi = 0; mi < 2; mi++) {
        unsigned off = (unsigned)((nw * 32 + mi * 16 + (lane & 15)) * XROWB
                                  + (lane >> 4) * 16);
        aA[mi] = sXa + off;
        aB[mi] = sXb + off;
    }
    // B-frag lane addresses: 4 x 16-col blocks per warp
    unsigned bA[4], bB[4];
    #pragma unroll
    for (int bi = 0; bi < 4; bi++) {
        unsigned off = (unsigned)((kw * 64 + bi * 16 + (m >> 1) * 8 + (lane & 7)) * XROWB
                                  + (m & 1) * 16);
        bA[bi] = sWm + off;
        bB[bi] = sWh + off;
    }

    // accumulators: [mi][nj][frag] for P (cf) and Q (cq); nj = bi*2 + {0,1}
    float cf[2][8][4], cq[2][8][4];
    #pragma unroll
    for (int mi = 0; mi < 2; mi++)
        #pragma unroll
        for (int nj = 0; nj < 8; nj++)
            #pragma unroll
            for (int p = 0; p < 4; p++) { cf[mi][nj][p] = 0.f; cq[mi][nj][p] = 0.f; }

    // ---- pipelined mainloop: ks 0..5 on group 0, ks 6..11 on group 1 ----
    asm volatile("cp.async.wait_group 1;");
    __syncthreads();

    #pragma unroll
    for (int half = 0; half < 2; half++) {
        #pragma unroll
        for (int kss = 0; kss < 6; kss++) {
            const int ks = half * 6 + kss;
            const unsigned off = (unsigned)(ks * 32);
            unsigned xa0[2], xa1[2], xa2[2], xa3[2];
            unsigned xb0[2], xb1[2], xb2[2], xb3[2];
            #pragma unroll
            for (int mi = 0; mi < 2; mi++) {
                ldsm_x4(xa0[mi], xa1[mi], xa2[mi], xa3[mi], aA[mi] + off);
                ldsm_x4(xb0[mi], xb1[mi], xb2[mi], xb3[mi], aB[mi] + off);
            }
            #pragma unroll
            for (int bi = 0; bi < 4; bi++) {
                unsigned wa0, wa1, wa2, wa3, wb0, wb1, wb2, wb3;
                ldsm_x4(wa0, wa1, wa2, wa3, bA[bi] + off);
                ldsm_x4(wb0, wb1, wb2, wb3, bB[bi] + off);
                #pragma unroll
                for (int mi = 0; mi < 2; mi++) {
                    mma_bf16(cf[mi][2 * bi],     xa0[mi], xa1[mi], xa2[mi], xa3[mi], wa0, wa1);
                    mma_bf16(cf[mi][2 * bi + 1], xa0[mi], xa1[mi], xa2[mi], xa3[mi], wa2, wa3);
                    mma_bf16(cq[mi][2 * bi],     xb0[mi], xb1[mi], xb2[mi], xb3[mi], wb0, wb1);
                    mma_bf16(cq[mi][2 * bi + 1], xb0[mi], xb1[mi], xb2[mi], xb3[mi], wb2, wb3);
                }
            }
        }
        if (half == 0) {
            asm volatile("cp.async.wait_group 0;");
            __syncthreads();
        }
    }

    // ---- in-register dot over v, reduce over q via shfl ----
    // col of frag nj elem 0/1 = kw*64 + nj*8 + 2q (+1) -> k_local = kw*4 + (nj>>1)
    float sl[2][4], sh[2][4];
    #pragma unroll
    for (int mi = 0; mi < 2; mi++)
        #pragma unroll
        for (int kx = 0; kx < 4; kx++) { sl[mi][kx] = 0.f; sh[mi][kx] = 0.f; }
    #pragma unroll
    for (int mi = 0; mi < 2; mi++)
        #pragma unroll
        for (int nj = 0; nj < 8; nj++) {
            int kx = nj >> 1;
            sl[mi][kx] = fmaf(cf[mi][nj][0], cq[mi][nj][0],
                         fmaf(cf[mi][nj][1], cq[mi][nj][1], sl[mi][kx]));
            sh[mi][kx] = fmaf(cf[mi][nj][2], cq[mi][nj][2],
                         fmaf(cf[mi][nj][3], cq[mi][nj][3], sh[mi][kx]));
        }
    #pragma unroll
    for (int mi = 0; mi < 2; mi++)
        #pragma unroll
        for (int kx = 0; kx < 4; kx++) {
            sl[mi][kx] += __shfl_xor_sync(0xffffffffu, sl[mi][kx], 1);
            sl[mi][kx] += __shfl_xor_sync(0xffffffffu, sl[mi][kx], 2);
            sh[mi][kx] += __shfl_xor_sync(0xffffffffu, sh[mi][kx], 1);
            sh[mi][kx] += __shfl_xor_sync(0xffffffffu, sh[mi][kx], 2);
        }
    if (q == 0) {
        #pragma unroll
        for (int mi = 0; mi < 2; mi++) {
            int n0 = ntile + nw * 32 + mi * 16 + g;
            int n1 = n0 + 8;
            #pragma unroll
            for (int kx = 0; kx < 4; kx++) {
                int k = k0 + kw * 4 + kx;
                out[(n0 >> 4) * 1024 + k * 16 + (n0 & 15)] = sl[mi][kx];
                out[(n1 >> 4) * 1024 + k * 16 + (n1 & 15)] = sh[mi][kx];
            }
        }
    }
}

extern "C" void kernel_launch(void* const* d_in, const int* in_sizes, int n_in,
                              void* d_out, int out_size) {
    (void)in_sizes; (void)n_in; (void)out_size;
    const float* x0 = (const float*)d_in[0];
    // d_in[1] (x_h) intentionally unused: reference recomputes it from x_0.
    const float* Vm = (const float*)d_in[2];
    const float* Vh = (const float*)d_in[3];
    float* out = (float*)d_out;

    cudaFuncSetAttribute(cin_mma_kernel,
                         cudaFuncAttributeMaxDynamicSharedMemorySize, SMEM_MAIN);

    prep_kernel<<<256, 128>>>(x0, Vm, Vh);
    dim3 grid(8, 16);    // (kv-tiles of 128 cols, n-tiles of 128 rows) = 128 CTAs
    cin_mma_kernel<<<grid, NTHR2, SMEM_MAIN>>>(out);
}

// round 16
// speedup vs baseline: 1.1572x; 1.1572x over previous
#include <cuda_runtime.h>
#include <cuda_bf16.h>

// Problem constants (fixed by setup_inputs):
// x_0  : [128, 64, 16] f32   (d_in[0])
// x_h  : [128, 64, 16] f32   (d_in[1], UNUSED — reference bug recomputes from x_0)
// Vm   : [64, 1, 64, 16] f32 (d_in[2])
// Vh   : [64, 1, 16, 64] f32 (d_in[3])
// out  : [128, 64, 16] f32
//
// out[b,k,d] = sum_v P[n,kv]*Q[n,kv], n = b*16+d, kv = k*16+v
//   P = Xa[2048x64] * Wm^T,  Q = Xb[2048x64] * Wh^T
// bf16 3-term split folded into K=192: X=[hi|lo|hi], W=[whi|whi|wlo]
// -> X*W = hi*whi + lo*whi + hi*wlo (residual ~2^-18).
//
// R16: SINGLE fused kernel. Each CTA (128n x 128kv) loads its own f32 inputs
// (96KB, L2-hot) with coalesced LDG.128, converts to composite bf16 in
// registers, stores directly into the smem operand layout, then runs the
// R15 mainloop (ldmatrix.x4 + HMMA interleaved A/B) and in-register dot.

#define XROWB 400        // padded smem row stride in bytes (192 bf16 + 16B pad)
#define SMEM_MAIN 204800 // 4 regions x 128 rows x 400 B
#define NTHR 256
#define RSZ 51200u

__device__ __forceinline__ void ldsm_x4(unsigned& r0, unsigned& r1,
                                        unsigned& r2, unsigned& r3,
                                        unsigned addr) {
    asm volatile("ldmatrix.sync.aligned.m8n8.x4.shared.b16 {%0,%1,%2,%3}, [%4];"
        : "=r"(r0), "=r"(r1), "=r"(r2), "=r"(r3) : "r"(addr));
}
__device__ __forceinline__ void mma_bf16(float c[4],
        unsigned a0, unsigned a1, unsigned a2, unsigned a3,
        unsigned b0, unsigned b1) {
    asm volatile(
        "mma.sync.aligned.m16n8k16.row.col.f32.bf16.bf16.f32 "
        "{%0,%1,%2,%3},{%4,%5,%6,%7},{%8,%9},{%0,%1,%2,%3};"
        : "+f"(c[0]), "+f"(c[1]), "+f"(c[2]), "+f"(c[3])
        : "r"(a0), "r"(a1), "r"(a2), "r"(a3), "r"(b0), "r"(b1));
}
__device__ __forceinline__ void sts16(unsigned addr, unsigned short v) {
    asm volatile("st.shared.u16 [%0], %1;" :: "r"(addr), "h"(v));
}
__device__ __forceinline__ void sts32(unsigned addr, unsigned v) {
    asm volatile("st.shared.u32 [%0], %1;" :: "r"(addr), "r"(v));
}
__device__ __forceinline__ unsigned short bhi(float v) {
    return __bfloat16_as_ushort(__float2bfloat16(v));
}
__device__ __forceinline__ unsigned short blo(float v, unsigned short h) {
    float hf = __bfloat162float(__ushort_as_bfloat16(h));
    return __bfloat16_as_ushort(__float2bfloat16(v - hf));
}

__global__ void __launch_bounds__(NTHR, 1)
cin_fused_kernel(const float* __restrict__ x0,
                 const float* __restrict__ Vm,
                 const float* __restrict__ Vh,
                 float* __restrict__ out)
{
    extern __shared__ __align__(16) unsigned char smem[];
    const unsigned sXa = (unsigned)__cvta_generic_to_shared(smem);
    const unsigned sXb = sXa + RSZ;
    const unsigned sWm = sXa + 2u * RSZ;
    const unsigned sWh = sXa + 3u * RSZ;

    const int tid   = threadIdx.x;
    const int k0    = blockIdx.x * 8;     // 8 k per CTA (128 kv cols)
    const int ntile = blockIdx.y * 128;   // 128 n rows
    const int b0    = ntile >> 4;         // 8 b per CTA

    // ================= staging: load f32, convert, store composite =========
    {
        // one float4 per thread per tile (256 f4 = 1024 floats = full tile)
        float4 xw[8], vmw[8], vhw[8];
        const float4* x4  = reinterpret_cast<const float4*>(x0);
        const float4* vm4 = reinterpret_cast<const float4*>(Vm);
        const float4* vh4 = reinterpret_cast<const float4*>(Vh);
        #pragma unroll
        for (int t = 0; t < 8; t++) {
            xw[t]  = x4[(b0 + t) * 256 + tid];
            vmw[t] = vm4[(k0 + t) * 256 + tid];
            vhw[t] = vh4[(k0 + t) * 256 + tid];
        }

        const int m0  = tid * 4;           // flat element base within a tile
        const int i0  = m0 >> 4;           // for [i,16]-major views (Xa/Wm)
        const int d0  = m0 & 15;
        const int rowf = m0 >> 6;          // for flat [*,64] views (Xb/Wh)
        const int j0   = m0 & 63;

        #pragma unroll
        for (int t = 0; t < 8; t++) {
            // ---- X tile b0+t ----
            {
                float vals[4] = {xw[t].x, xw[t].y, xw[t].z, xw[t].w};
                unsigned short hi[4], lo[4];
                #pragma unroll
                for (int e = 0; e < 4; e++) {
                    hi[e] = bhi(vals[e]);
                    lo[e] = blo(vals[e], hi[e]);
                }
                // Xa[n = (b-b0)*16 + d][col i], segs [hi|lo|hi]
                // m = m0+e: d = d0+e (d0 multiple of 4, no carry), i = i0
                #pragma unroll
                for (int e = 0; e < 4; e++) {
                    unsigned base = sXa + (unsigned)((t * 16 + d0 + e) * XROWB + i0 * 2);
                    sts16(base,        hi[e]);
                    sts16(base + 128u, lo[e]);
                    sts16(base + 256u, hi[e]);
                }
                // Xb[n = t*16 + (m>>6)][col j = m&63], segs [hi|lo|hi], packed
                unsigned hA = (unsigned)hi[0] | ((unsigned)hi[1] << 16);
                unsigned hB = (unsigned)hi[2] | ((unsigned)hi[3] << 16);
                unsigned lA = (unsigned)lo[0] | ((unsigned)lo[1] << 16);
                unsigned lB = (unsigned)lo[2] | ((unsigned)lo[3] << 16);
                unsigned base = sXb + (unsigned)((t * 16 + rowf) * XROWB + j0 * 2);
                sts32(base,        hA); sts32(base + 4u,   hB);
                sts32(base + 128u, lA); sts32(base + 132u, lB);
                sts32(base + 256u, hA); sts32(base + 260u, hB);
            }
            // ---- Wm tile k0+t: Wm[kv=(t)*16+v][col i], segs [hi|hi|lo] ----
            {
                float vals[4] = {vmw[t].x, vmw[t].y, vmw[t].z, vmw[t].w};
                #pragma unroll
                for (int e = 0; e < 4; e++) {
                    unsigned short hi = bhi(vals[e]);
                    unsigned short lo = blo(vals[e], hi);
                    unsigned base = sWm + (unsigned)((t * 16 + d0 + e) * XROWB + i0 * 2);
                    sts16(base,        hi);
                    sts16(base + 128u, hi);
                    sts16(base + 256u, lo);
                }
            }
            // ---- Wh tile k0+t: Wh[kv=t*16+v][col j], segs [hi|hi|lo], packed ----
            {
                float vals[4] = {vhw[t].x, vhw[t].y, vhw[t].z, vhw[t].w};
                unsigned short hi[4], lo[4];
                #pragma unroll
                for (int e = 0; e < 4; e++) {
                    hi[e] = bhi(vals[e]);
                    lo[e] = blo(vals[e], hi[e]);
                }
                unsigned hA = (unsigned)hi[0] | ((unsigned)hi[1] << 16);
                unsigned hB = (unsigned)hi[2] | ((unsigned)hi[3] << 16);
                unsigned lA = (unsigned)lo[0] | ((unsigned)lo[1] << 16);
                unsigned lB = (unsigned)lo[2] | ((unsigned)lo[3] << 16);
                unsigned base = sWh + (unsigned)((t * 16 + rowf) * XROWB + j0 * 2);
                sts32(base,        hA); sts32(base + 4u,   hB);
                sts32(base + 128u, hA); sts32(base + 132u, hB);
                sts32(base + 256u, lA); sts32(base + 260u, lB);
            }
        }
    }
    __syncthreads();

    // ================= mainloop (R15 core) =================================
    // warp w: nw = w&3 (rows nw*32), kw = w>>2 (cols kw*64)
    const int w    = tid >> 5;
    const int lane = tid & 31;
    const int nw   = w & 3;
    const int kw   = w >> 2;
    const int g    = lane >> 2;
    const int q    = lane & 3;
    const int m    = lane >> 3;

    unsigned aA[2], aB[2];
    #pragma unroll
    for (int mi = 0; mi < 2; mi++) {
        unsigned off = (unsigned)((nw * 32 + mi * 16 + (lane & 15)) * XROWB
                                  + (lane >> 4) * 16);
        aA[mi] = sXa + off;
        aB[mi] = sXb + off;
    }
    unsigned bA[4], bB[4];
    #pragma unroll
    for (int bi = 0; bi < 4; bi++) {
        unsigned off = (unsigned)((kw * 64 + bi * 16 + (m >> 1) * 8 + (lane & 7)) * XROWB
                                  + (m & 1) * 16);
        bA[bi] = sWm + off;
        bB[bi] = sWh + off;
    }

    float cf[2][8][4], cq[2][8][4];
    #pragma unroll
    for (int mi = 0; mi < 2; mi++)
        #pragma unroll
        for (int nj = 0; nj < 8; nj++)
            #pragma unroll
            for (int p = 0; p < 4; p++) { cf[mi][nj][p] = 0.f; cq[mi][nj][p] = 0.f; }

    #pragma unroll
    for (int ks = 0; ks < 12; ks++) {
        const unsigned off = (unsigned)(ks * 32);
        unsigned xa0[2], xa1[2], xa2[2], xa3[2];
        unsigned xb0[2], xb1[2], xb2[2], xb3[2];
        #pragma unroll
        for (int mi = 0; mi < 2; mi++) {
            ldsm_x4(xa0[mi], xa1[mi], xa2[mi], xa3[mi], aA[mi] + off);
            ldsm_x4(xb0[mi], xb1[mi], xb2[mi], xb3[mi], aB[mi] + off);
        }
        #pragma unroll
        for (int bi = 0; bi < 4; bi++) {
            unsigned wa0, wa1, wa2, wa3, wb0, wb1, wb2, wb3;
            ldsm_x4(wa0, wa1, wa2, wa3, bA[bi] + off);
            ldsm_x4(wb0, wb1, wb2, wb3, bB[bi] + off);
            #pragma unroll
            for (int mi = 0; mi < 2; mi++) {
                mma_bf16(cf[mi][2 * bi],     xa0[mi], xa1[mi], xa2[mi], xa3[mi], wa0, wa1);
                mma_bf16(cf[mi][2 * bi + 1], xa0[mi], xa1[mi], xa2[mi], xa3[mi], wa2, wa3);
                mma_bf16(cq[mi][2 * bi],     xb0[mi], xb1[mi], xb2[mi], xb3[mi], wb0, wb1);
                mma_bf16(cq[mi][2 * bi + 1], xb0[mi], xb1[mi], xb2[mi], xb3[mi], wb2, wb3);
            }
        }
    }

    // ================= epilogue: in-register dot over v =====================
    float sl[2][4], sh[2][4];
    #pragma unroll
    for (int mi = 0; mi < 2; mi++)
        #pragma unroll
        for (int kx = 0; kx < 4; kx++) { sl[mi][kx] = 0.f; sh[mi][kx] = 0.f; }
    #pragma unroll
    for (int mi = 0; mi < 2; mi++)
        #pragma unroll
        for (int nj = 0; nj < 8; nj++) {
            int kx = nj >> 1;
            sl[mi][kx] = fmaf(cf[mi][nj][0], cq[mi][nj][0],
                         fmaf(cf[mi][nj][1], cq[mi][nj][1], sl[mi][kx]));
            sh[mi][kx] = fmaf(cf[mi][nj][2], cq[mi][nj][2],
                         fmaf(cf[mi][nj][3], cq[mi][nj][3], sh[mi][kx]));
        }
    #pragma unroll
    for (int mi = 0; mi < 2; mi++)
        #pragma unroll
        for (int kx = 0; kx < 4; kx++) {
            sl[mi][kx] += __shfl_xor_sync(0xffffffffu, sl[mi][kx], 1);
            sl[mi][kx] += __shfl_xor_sync(0xffffffffu, sl[mi][kx], 2);
            sh[mi][kx] += __shfl_xor_sync(0xffffffffu, sh[mi][kx], 1);
            sh[mi][kx] += __shfl_xor_sync(0xffffffffu, sh[mi][kx], 2);
        }
    if (q == 0) {
        #pragma unroll
        for (int mi = 0; mi < 2; mi++) {
            int n0 = ntile + nw * 32 + mi * 16 + g;
            int n1 = n0 + 8;
            #pragma unroll
            for (int kx = 0; kx < 4; kx++) {
                int k = k0 + kw * 4 + kx;
                out[(n0 >> 4) * 1024 + k * 16 + (n0 & 15)] = sl[mi][kx];
                out[(n1 >> 4) * 1024 + k * 16 + (n1 & 15)] = sh[mi][kx];
            }
        }
    }
}

extern "C" void kernel_launch(void* const* d_in, const int* in_sizes, int n_in,
                              void* d_out, int out_size) {
    (void)in_sizes; (void)n_in; (void)out_size;
    const float* x0 = (const float*)d_in[0];
    // d_in[1] (x_h) intentionally unused: reference recomputes it from x_0.
    const float* Vm = (const float*)d_in[2];
    const float* Vh = (const float*)d_in[3];
    float* out = (float*)d_out;

    cudaFuncSetAttribute(cin_fused_kernel,
                         cudaFuncAttributeMaxDynamicSharedMemorySize, SMEM_MAIN);

    dim3 grid(8, 16);    // (kv-tiles of 128 cols, n-tiles of 128 rows) = 128 CTAs
    cin_fused_kernel<<<grid, NTHR, SMEM_MAIN>>>(x0, Vm, Vh, out);
}